// round 1
// baseline (speedup 1.0000x reference)
#include <cuda_runtime.h>
#include <cstdint>

#define DINLINE __device__ __forceinline__

static constexpr int MAXN = 2048;
static constexpr int FIN  = 128;
static constexpr int KC   = 1152;   // 128 base cols + 1024 spline cols (m*8+g)

// ---- scratch (device globals: no allocation allowed) ----
__device__ __align__(16) float g_W[FIN * KC];            // [i][c]  0.59 MB
__device__ __align__(16) float g_A[5 * MAXN * FIN];      // [sel][n][i] 5.25 MB (sel: 0=silu, 1..4=bspl_j)
__device__ __align__(16) float g_C[MAXN * KC];           // [n][c]  9.44 MB
__device__ unsigned char g_cfl[MAXN * FIN];              // [n][m]

// ---- tiny PTX helpers ----
DINLINE void cp16(void* s, const void* g) {
    unsigned sa = (unsigned)__cvta_generic_to_shared(s);
    asm volatile("cp.async.cg.shared.global [%0], [%1], 16;" :: "r"(sa), "l"(g));
}
DINLINE void cp_commit_wait() {
    asm volatile("cp.async.commit_group;");
    asm volatile("cp.async.wait_group 0;");
}
DINLINE unsigned long long dup2(float a) {
    unsigned long long r;
    asm("mov.b64 %0, {%1, %1};" : "=l"(r) : "f"(a));
    return r;
}
DINLINE unsigned long long ffma2(unsigned long long a, unsigned long long b, unsigned long long c) {
    unsigned long long d;
    asm("fma.rn.f32x2 %0, %1, %2, %3;" : "=l"(d) : "l"(a), "l"(b), "l"(c));
    return d;
}
DINLINE void unpack2(unsigned long long v, float& lo, float& hi) {
    asm("mov.b64 {%0, %1}, %2;" : "=f"(lo), "=f"(hi) : "l"(v));
}
DINLINE void lds_w(const float* p, unsigned long long& w0, unsigned long long& w1) {
    unsigned sa = (unsigned)__cvta_generic_to_shared(p);
    asm("ld.shared.v2.b64 {%0, %1}, [%2];" : "=l"(w0), "=l"(w1) : "r"(sa));
}

// ---- K1a: build combined weight W[i][c]: c<128 -> base_weight[c][i]; c>=128 -> spline[i][c-128] ----
__global__ void k_prep_w(const float* __restrict__ bw, const float* __restrict__ sw) {
    const int i = blockIdx.x;     // 0..127 (input feature = K index)
    const int t = threadIdx.x;    // 0..127
    g_W[i * KC + t] = bw[t * FIN + i];
#pragma unroll
    for (int it = 0; it < 8; ++it)
        g_W[i * KC + 128 + it * 128 + t] = sw[i * 1024 + it * 128 + t];
}

// ---- K1b: activations: silu, 4 bspline coeffs, cfloor ----
__global__ void k_prep_a(const float* __restrict__ x, int total) {
    int idx = blockIdx.x * blockDim.x + threadIdx.x;
    if (idx >= total) return;
    float xv = x[idx];
    float sx = xv / (1.0f + __expf(-xv));                 // silu
    float xn = fminf(fmaxf(xv, -1.0f), 1.0f);             // clip (shift=0, scale=1)
    float t  = (xn + 2.2f) * 2.5f;                        // (xn - G0)/H, G0=-2.2, H=0.4
    float fl = floorf(t);
    float u  = t - fl;                                    // NOTE: unclipped floor (matches ref)
    int ii = (int)fl; ii = ii < 3 ? 3 : (ii > 7 ? 7 : ii);
    const float s6 = 0.16666666666666666f;
    float u2 = u * u;
    float b0 = s6 * (1.0f + u * (-3.0f + u * (3.0f - u)));      // (1-3u+3u^2-u^3)/6
    float b1 = s6 * (4.0f + u2 * (3.0f * u - 6.0f));            // (4-6u^2+3u^3)/6
    float b2 = s6 * (1.0f + u * (3.0f + u * (3.0f - 3.0f * u))); // (1+3u+3u^2-3u^3)/6
    float b3 = s6 * (u2 * u);                                    // u^3/6
    g_A[idx]                  = sx;
    g_A[1 * MAXN * FIN + idx] = b0;
    g_A[2 * MAXN * FIN + idx] = b1;
    g_A[3 * MAXN * FIN + idx] = b2;
    g_A[4 * MAXN * FIN + idx] = b3;
    g_cfl[idx] = (unsigned char)(ii - 3);
}

// ---- K2: C[n][c] = sum_i A_sel[n][i] * W[i][c]; M=2048, N=1152, K=128 (fp32, f32x2 packed) ----
// Grid: (N/32, 9). col-tile ct selects A matrix: ct==0 -> silu, else bspl_{(ct-1)>>1}.
__global__ void __launch_bounds__(256) k_gemm() {
    extern __shared__ float sm[];
    float* sA = sm;                 // 32 rows x 132 (padded) floats
    float* sW = sm + 32 * 132;      // 128 x 128 floats
    const int ct  = blockIdx.y;
    const int m0  = blockIdx.x * 32;
    const int sel = (ct == 0) ? 0 : 1 + ((ct - 1) >> 1);
    const float* Ag = g_A + sel * (MAXN * FIN);
    const int tid = threadIdx.x;

    // stage A tile (16KB) and W tile (64KB) via cp.async
#pragma unroll
    for (int it = 0; it < 4; ++it) {
        int f = tid + it * 256;
        int r = f >> 5, c4 = f & 31;
        cp16(&sA[r * 132 + c4 * 4], Ag + (m0 + r) * FIN + c4 * 4);
    }
#pragma unroll
    for (int it = 0; it < 16; ++it) {
        int f = tid + it * 256;
        int r = f >> 5, c4 = f & 31;
        cp16(&sW[r * 128 + c4 * 4], g_W + r * KC + ct * 128 + c4 * 4);
    }
    cp_commit_wait();
    __syncthreads();

    // warp tile 16 rows x 32 cols; thread: 4 rows (stride 4) x 4 cols
    const int warp = tid >> 5, lane = tid & 31;
    const int wr = warp >> 2, wc = warp & 3;
    const int lr = lane >> 3, lcg = lane & 7;
    const int r0 = wr * 16 + lr;           // + {0,4,8,12}
    const int c0 = wc * 32 + lcg * 4;      // 4 consecutive cols = 2 f32x2

    unsigned long long acc[4][2];
#pragma unroll
    for (int i = 0; i < 4; ++i) { acc[i][0] = 0ull; acc[i][1] = 0ull; }

#pragma unroll 8
    for (int kb = 0; kb < 32; ++kb) {
        float4 av[4];
#pragma unroll
        for (int rr = 0; rr < 4; ++rr)
            av[rr] = *(const float4*)&sA[(r0 + rr * 4) * 132 + kb * 4];
#pragma unroll
        for (int kk = 0; kk < 4; ++kk) {
            unsigned long long w0, w1;
            lds_w(&sW[(kb * 4 + kk) * 128 + c0], w0, w1);
#pragma unroll
            for (int rr = 0; rr < 4; ++rr) {
                float a = (kk == 0) ? av[rr].x : (kk == 1) ? av[rr].y : (kk == 2) ? av[rr].z : av[rr].w;
                unsigned long long ad = dup2(a);
                acc[rr][0] = ffma2(ad, w0, acc[rr][0]);
                acc[rr][1] = ffma2(ad, w1, acc[rr][1]);
            }
        }
    }

#pragma unroll
    for (int rr = 0; rr < 4; ++rr) {
        float4 o;
        unpack2(acc[rr][0], o.x, o.y);
        unpack2(acc[rr][1], o.z, o.w);
        *(float4*)&g_C[(m0 + r0 + rr * 4) * KC + ct * 128 + c0] = o;
    }
}

// ---- K3: out[n][o] = C[n][o] + sum_jp C[n][128 + jp*256 + (o>>2)*8 + cfl[n][32jp+(o>>2)] + (o&3)] ----
__global__ void k_final(float* __restrict__ out, int total) {
    int idx = blockIdx.x * blockDim.x + threadIdx.x;
    if (idx >= total) return;
    int n = idx >> 7, o = idx & 127;
    int q = o >> 2, r2 = o & 3;
    const float* Crow = g_C + n * KC;
    const unsigned char* cf = g_cfl + (n << 7);
    float acc = Crow[o];
#pragma unroll
    for (int jp = 0; jp < 4; ++jp) {
        int g = (int)cf[jp * 32 + q] + r2;
        acc += Crow[128 + jp * 256 + q * 8 + g];
    }
    out[idx] = acc;
}

extern "C" void kernel_launch(void* const* d_in, const int* in_sizes, int n_in,
                              void* d_out, int out_size) {
    const float* x  = (const float*)d_in[0];
    const float* bw = (const float*)d_in[1];
    const float* sw = (const float*)d_in[2];
    float* out = (float*)d_out;
    int N = in_sizes[0] / FIN;
    if (N > MAXN) N = MAXN;
    int total = N * FIN;

    const int smem = (32 * 132 + 128 * 128) * (int)sizeof(float);  // 82,432 B
    cudaFuncSetAttribute(k_gemm, cudaFuncAttributeMaxDynamicSharedMemorySize, smem);

    k_prep_w<<<128, 128>>>(bw, sw);
    k_prep_a<<<(total + 255) / 256, 256>>>(x, total);
    dim3 grid(N / 32, 9);
    k_gemm<<<grid, 256, smem>>>();
    k_final<<<(total + 255) / 256, 256>>>(out, total);
}

// round 3
// speedup vs baseline: 1.7496x; 1.7496x over previous
#include <cuda_runtime.h>
#include <cuda_bf16.h>
#include <cstdint>

#define DINLINE __device__ __forceinline__

static constexpr int MAXN = 2048;
static constexpr int FIN  = 128;
static constexpr int KC   = 1152;   // 128 base cols + 1024 spline cols (m*8+g)

// ---- scratch (device globals; no allocation allowed) ----
__device__ __align__(16) __nv_bfloat16 g_Abf[5][MAXN][256]; // [sel][n][0:128)=hi,[128:256)=lo
__device__ __align__(16) __nv_bfloat16 g_Wbf[2][KC][128];   // [0]=hi,[1]=lo; N-major: [c][k]
__device__ __align__(16) float g_C[MAXN * KC];
__device__ unsigned char g_cfl[MAXN * FIN];

// ---------------- PTX helpers ----------------
DINLINE uint32_t smem_u32(const void* p) {
    uint32_t a;
    asm("{ .reg .u64 t; cvta.to.shared.u64 t, %1; cvt.u32.u64 %0, t; }" : "=r"(a) : "l"(p));
    return a;
}
DINLINE void cp16(uint32_t s, const void* g) {
    asm volatile("cp.async.cg.shared.global [%0], [%1], 16;" :: "r"(s), "l"(g));
}
DINLINE void cp_commit_wait() {
    asm volatile("cp.async.commit_group;");
    asm volatile("cp.async.wait_group 0;");
}
DINLINE void ldsm_x4(uint32_t& r0, uint32_t& r1, uint32_t& r2, uint32_t& r3, uint32_t addr) {
    asm volatile("ldmatrix.sync.aligned.m8n8.x4.shared.b16 {%0,%1,%2,%3}, [%4];"
                 : "=r"(r0), "=r"(r1), "=r"(r2), "=r"(r3) : "r"(addr));
}
DINLINE void mma16816(float* d, const uint32_t* a, const uint32_t* b) {
    asm volatile(
        "mma.sync.aligned.m16n8k16.row.col.f32.bf16.bf16.f32 "
        "{%0,%1,%2,%3}, {%4,%5,%6,%7}, {%8,%9}, {%0,%1,%2,%3};"
        : "+f"(d[0]), "+f"(d[1]), "+f"(d[2]), "+f"(d[3])
        : "r"(a[0]), "r"(a[1]), "r"(a[2]), "r"(a[3]), "r"(b[0]), "r"(b[1]));
}

// ---- K1a: W hi/lo, N-major: g_Wbf[part][c][i] ----
__global__ void k_prep_w(const float* __restrict__ bw, const float* __restrict__ sw) {
    const int c = blockIdx.x;   // 0..1151
    const int i = threadIdx.x;  // 0..127 (k index)
    float w = (c < 128) ? bw[c * FIN + i] : sw[i * 1024 + (c - 128)];
    __nv_bfloat16 hi = __float2bfloat16(w);
    __nv_bfloat16 lo = __float2bfloat16(w - __bfloat162float(hi));
    g_Wbf[0][c][i] = hi;
    g_Wbf[1][c][i] = lo;
}

// ---- K1b: activations -> bf16 hi/lo planes + cfloor ----
__global__ void k_prep_a(const float* __restrict__ x, int total) {
    int idx = blockIdx.x * blockDim.x + threadIdx.x;
    if (idx >= total) return;
    float xv = x[idx];
    float sx = xv / (1.0f + __expf(-xv));
    float xn = fminf(fmaxf(xv, -1.0f), 1.0f);
    float t  = (xn + 2.2f) * 2.5f;
    float fl = floorf(t);
    float u  = t - fl;
    int ii = (int)fl; ii = ii < 3 ? 3 : (ii > 7 ? 7 : ii);
    const float s6 = 0.16666666666666666f;
    float u2 = u * u;
    float v[5];
    v[0] = sx;
    v[1] = s6 * (1.0f + u * (-3.0f + u * (3.0f - u)));
    v[2] = s6 * (4.0f + u2 * (3.0f * u - 6.0f));
    v[3] = s6 * (1.0f + u * (3.0f + u * (3.0f - 3.0f * u)));
    v[4] = s6 * (u2 * u);
    int n = idx >> 7, i = idx & 127;
#pragma unroll
    for (int s = 0; s < 5; ++s) {
        __nv_bfloat16 hi = __float2bfloat16(v[s]);
        __nv_bfloat16 lo = __float2bfloat16(v[s] - __bfloat162float(hi));
        g_Abf[s][n][i] = hi;
        g_Abf[s][n][128 + i] = lo;
    }
    g_cfl[idx] = (unsigned char)(ii - 3);
}

// ---- K2: HMMA GEMM via mma.sync m16n8k16 bf16. C = A''W'' (3 hi/lo passes, K=384) ----
// grid (M/128, 9), 256 threads. smem: A tile 64KB (128 rows x 512B, hi|lo) + W 2x32KB.
// XOR swizzle: 16B chunk q at row r stored at chunk (q ^ (r&7)).
__global__ void __launch_bounds__(256) k_gemm_mma() {
    extern __shared__ __align__(128) char smem[];
    const uint32_t OF_W = 65536;
    const uint32_t sb = smem_u32(smem);
    const int tid = threadIdx.x, lane = tid & 31, wid = tid >> 5;
    const int m0 = blockIdx.x * 128, ct = blockIdx.y;
    const int sel = (ct == 0) ? 0 : 1 + ((ct - 1) >> 1);

    // ---- stage A (hi|lo interleaved per row) ----
    const __nv_bfloat16* Asrc = &g_Abf[sel][m0][0];
#pragma unroll
    for (int it = 0; it < 16; ++it) {
        int idx = it * 256 + tid;
        int row = idx >> 5, q = idx & 31;          // 32 chunks of 16B per 512B row
        cp16(sb + row * 512 + (((q & 24) | ((q ^ row) & 7)) * 16), Asrc + row * 256 + q * 8);
    }
    // ---- stage W hi, lo ----
#pragma unroll
    for (int p = 0; p < 2; ++p)
#pragma unroll
        for (int it = 0; it < 8; ++it) {
            int idx = it * 256 + tid;
            int row = idx >> 4, q = idx & 15;      // 16 chunks per 256B row
            cp16(sb + OF_W + p * 32768 + row * 256 + (((q & 8) | ((q ^ row) & 7)) * 16),
                 &g_Wbf[p][ct * 128 + row][q * 8]);
        }
    cp_commit_wait();
    __syncthreads();

    const int wm = wid >> 2, wn = wid & 3;         // warp tile: 64 rows x 32 cols
    float acc[4][4][4];
#pragma unroll
    for (int i = 0; i < 4; ++i)
#pragma unroll
        for (int j = 0; j < 4; ++j)
#pragma unroll
            for (int k = 0; k < 4; ++k) acc[i][j][k] = 0.0f;

    // A ldmatrix lane mapping: lanes 0-15 rows, lanes 16-31 rows @ chunk+1
    const int a_lrow = wm * 64 + (lane & 15);
    const int a_lsel = lane >> 4;
    // B ldmatrix lane mapping: mats = (n0..7,k0),(n0..7,k1),(n8..15,k0),(n8..15,k1)
    const int b_lrow0 = wn * 32 + ((lane >> 4) << 3) + (lane & 7);
    const int b_lsel = (lane >> 3) & 1;

    const int a_base[3] = {0, 16, 0};              // hi, lo, hi  (chunk offset)
    const uint32_t w_off[3] = {0, 0, 32768};       // hi, hi, lo

#pragma unroll
    for (int p = 0; p < 3; ++p) {
#pragma unroll
        for (int ks = 0; ks < 8; ++ks) {
            uint32_t af[4][4];
#pragma unroll
            for (int mt = 0; mt < 4; ++mt) {
                int row = a_lrow + mt * 16;
                int q = a_base[p] + ks * 2 + a_lsel;
                uint32_t addr = sb + row * 512 + (((q & 24) | ((q ^ row) & 7)) * 16);
                ldsm_x4(af[mt][0], af[mt][1], af[mt][2], af[mt][3], addr);
            }
            uint32_t bf[4][2];
#pragma unroll
            for (int h = 0; h < 2; ++h) {
                int row = b_lrow0 + h * 16;
                int q = ks * 2 + b_lsel;
                uint32_t addr = sb + OF_W + w_off[p] + row * 256
                              + (((q & 8) | ((q ^ row) & 7)) * 16);
                uint32_t r0, r1, r2, r3;
                ldsm_x4(r0, r1, r2, r3, addr);
                bf[h * 2][0] = r0; bf[h * 2][1] = r1;
                bf[h * 2 + 1][0] = r2; bf[h * 2 + 1][1] = r3;
            }
#pragma unroll
            for (int mt = 0; mt < 4; ++mt)
#pragma unroll
                for (int nt = 0; nt < 4; ++nt)
                    mma16816(acc[mt][nt], af[mt], bf[nt]);
        }
    }

    // ---- epilogue: fragment -> g_C ----
    const int er = lane >> 2, ec = (lane & 3) * 2;
#pragma unroll
    for (int mt = 0; mt < 4; ++mt) {
#pragma unroll
        for (int nt = 0; nt < 4; ++nt) {
            int row = m0 + wm * 64 + mt * 16 + er;
            int col = ct * 128 + wn * 32 + nt * 8 + ec;
            *(float2*)&g_C[row * KC + col]       = make_float2(acc[mt][nt][0], acc[mt][nt][1]);
            *(float2*)&g_C[(row + 8) * KC + col] = make_float2(acc[mt][nt][2], acc[mt][nt][3]);
        }
    }
}

// ---- K3: finalize, one block per row; C row staged in smem ----
__global__ void __launch_bounds__(128) k_final(float* __restrict__ out) {
    __shared__ float row[KC];
    const int n = blockIdx.x, tid = threadIdx.x;
    const float* Crow = g_C + n * KC;
#pragma unroll
    for (int it = 0; it < 9; ++it) row[it * 128 + tid] = Crow[it * 128 + tid];
    __syncthreads();
    const unsigned char* cf = g_cfl + (n << 7);
    int q = tid >> 2, r2 = tid & 3;
    float acc = row[tid];
#pragma unroll
    for (int jp = 0; jp < 4; ++jp)
        acc += row[128 + jp * 256 + q * 8 + (int)cf[jp * 32 + q] + r2];
    out[n * 128 + tid] = acc;
}

extern "C" void kernel_launch(void* const* d_in, const int* in_sizes, int n_in,
                              void* d_out, int out_size) {
    const float* x  = (const float*)d_in[0];
    const float* bw = (const float*)d_in[1];
    const float* sw = (const float*)d_in[2];
    float* out = (float*)d_out;
    int N = in_sizes[0] / FIN;
    if (N > MAXN) N = MAXN;
    int total = N * FIN;

    const int smem = 65536 + 65536;  // 128 KB
    cudaFuncSetAttribute(k_gemm_mma, cudaFuncAttributeMaxDynamicSharedMemorySize, smem);

    k_prep_w<<<KC, 128>>>(bw, sw);
    k_prep_a<<<(total + 255) / 256, 256>>>(x, total);
    dim3 grid(N / 128, 9);
    k_gemm_mma<<<grid, 256, smem>>>();
    k_final<<<N, 128>>>(out);
}

// round 4
// speedup vs baseline: 1.9589x; 1.1196x over previous
#include <cuda_runtime.h>
#include <cuda_bf16.h>
#include <cstdint>

#define DINLINE __device__ __forceinline__

static constexpr int MAXN = 2048;
static constexpr int FIN  = 128;

// ---- scratch (device globals; no allocation allowed) ----
__device__ __align__(16) __nv_bfloat16 g_Abf[5][MAXN][256]; // [sel][n][0:128)=hi,[128:256)=lo
__device__ __align__(16) __nv_bfloat16 g_Wbf[2][1152][128]; // [hi/lo][c][k] N-major
__device__ __align__(16) float g_Cs[MAXN * 1024];           // spline GEMM out [n][1024]
__device__ unsigned char g_cflp[MAXN * FIN];                // packed [n][q][jp]

// ---------------- PTX helpers ----------------
DINLINE uint32_t smem_u32(const void* p) {
    uint32_t a;
    asm("{ .reg .u64 t; cvta.to.shared.u64 t, %1; cvt.u32.u64 %0, t; }" : "=r"(a) : "l"(p));
    return a;
}
DINLINE void cp16(uint32_t s, const void* g) {
    asm volatile("cp.async.cg.shared.global [%0], [%1], 16;" :: "r"(s), "l"(g));
}
DINLINE void cp_commit() { asm volatile("cp.async.commit_group;"); }
template <int N_> DINLINE void cp_wait() {
    asm volatile("cp.async.wait_group %0;" :: "n"(N_));
}
DINLINE void ldsm_x4(uint32_t& r0, uint32_t& r1, uint32_t& r2, uint32_t& r3, uint32_t addr) {
    asm volatile("ldmatrix.sync.aligned.m8n8.x4.shared.b16 {%0,%1,%2,%3}, [%4];"
                 : "=r"(r0), "=r"(r1), "=r"(r2), "=r"(r3) : "r"(addr));
}
DINLINE void mma16816(float* d, const uint32_t* a, const uint32_t* b) {
    asm volatile(
        "mma.sync.aligned.m16n8k16.row.col.f32.bf16.bf16.f32 "
        "{%0,%1,%2,%3}, {%4,%5,%6,%7}, {%8,%9}, {%0,%1,%2,%3};"
        : "+f"(d[0]), "+f"(d[1]), "+f"(d[2]), "+f"(d[3])
        : "r"(a[0]), "r"(a[1]), "r"(a[2]), "r"(a[3]), "r"(b[0]), "r"(b[1]));
}

// ---- K1: all prep in one launch. Grid partition:
//   [0, PA)            : activations (256 thr, 2 elements-rows each... 1 elt/thread)
//   [PA, PA+64)        : base weight hi/lo (coalesced)
//   [PA+64, PA+64+128) : spline weight transpose (32x32 smem tiles)
__global__ void __launch_bounds__(256) k_prep(const float* __restrict__ x,
                                              const float* __restrict__ bw,
                                              const float* __restrict__ sw,
                                              int PA) {
    __shared__ float tile[32][33];
    const int b = blockIdx.x, t = threadIdx.x;
    if (b < PA) {
        int idx = b * 256 + t;
        float xv = x[idx];
        float sx = xv / (1.0f + __expf(-xv));
        float xn = fminf(fmaxf(xv, -1.0f), 1.0f);
        float tt = (xn + 2.2f) * 2.5f;
        float fl = floorf(tt);
        float u  = tt - fl;
        int ii = (int)fl; ii = ii < 3 ? 3 : (ii > 7 ? 7 : ii);
        const float s6 = 0.16666666666666666f;
        float u2 = u * u;
        float v[5];
        v[0] = sx;
        v[1] = s6 * (1.0f + u * (-3.0f + u * (3.0f - u)));
        v[2] = s6 * (4.0f + u2 * (3.0f * u - 6.0f));
        v[3] = s6 * (1.0f + u * (3.0f + u * (3.0f - 3.0f * u)));
        v[4] = s6 * (u2 * u);
        int n = idx >> 7, i = idx & 127;
#pragma unroll
        for (int s = 0; s < 5; ++s) {
            __nv_bfloat16 hi = __float2bfloat16(v[s]);
            __nv_bfloat16 lo = __float2bfloat16(v[s] - __bfloat162float(hi));
            g_Abf[s][n][i] = hi;
            g_Abf[s][n][128 + i] = lo;
        }
        // pack cfl: [n][q][jp], q=i&31, jp=i>>5
        g_cflp[n * 128 + (i & 31) * 4 + (i >> 5)] = (unsigned char)(ii - 3);
    } else if (b < PA + 64) {
        int f = (b - PA) * 256 + t;            // f = c*128 + i
        float w = bw[f];
        __nv_bfloat16 hi = __float2bfloat16(w);
        __nv_bfloat16 lo = __float2bfloat16(w - __bfloat162float(hi));
        int c = f >> 7, i = f & 127;
        g_Wbf[0][c][i] = hi;
        g_Wbf[1][c][i] = lo;
    } else {
        int bb = b - PA - 64;                  // 0..127
        int bc = bb >> 2, bi = bb & 3;         // c-tile (32 wide), i-tile (32 wide)
        int tx = t & 31, ty = t >> 5;          // tx: fast dim
#pragma unroll
        for (int iy = 0; iy < 4; ++iy) {
            int il = ty + 8 * iy;              // local i 0..31
            tile[il][tx] = sw[(bi * 32 + il) * 1024 + bc * 32 + tx];  // coalesced in c
        }
        __syncthreads();
#pragma unroll
        for (int iy = 0; iy < 4; ++iy) {
            int cl = ty + 8 * iy;              // local c 0..31
            float w = tile[tx][cl];
            __nv_bfloat16 hi = __float2bfloat16(w);
            __nv_bfloat16 lo = __float2bfloat16(w - __bfloat162float(hi));
            int c = 128 + bc * 32 + cl, i = bi * 32 + tx;  // coalesced in i
            g_Wbf[0][c][i] = hi;
            g_Wbf[1][c][i] = lo;
        }
    }
}

// ---- K2: HMMA GEMM, pipelined hi/lo staging. grid (M/128, 9), 256 thr. ----
struct Frag { float a[4][4][4]; };

DINLINE void gemm_pass(uint32_t sb, int a_chunk, uint32_t w_off,
                       int a_lrow, int a_lsel, int b_lrow0, int b_lsel,
                       float (&acc)[4][4][4]) {
#pragma unroll
    for (int ks = 0; ks < 8; ++ks) {
        uint32_t af[4][4];
#pragma unroll
        for (int mt = 0; mt < 4; ++mt) {
            int row = a_lrow + mt * 16;
            int q = a_chunk + ks * 2 + a_lsel;
            uint32_t addr = sb + row * 512 + (((q & 24) | ((q ^ row) & 7)) * 16);
            ldsm_x4(af[mt][0], af[mt][1], af[mt][2], af[mt][3], addr);
        }
        uint32_t bf[4][2];
#pragma unroll
        for (int h = 0; h < 2; ++h) {
            int row = b_lrow0 + h * 16;
            int q = ks * 2 + b_lsel;
            uint32_t addr = sb + 65536 + w_off + row * 256 + (((q & 8) | ((q ^ row) & 7)) * 16);
            uint32_t r0, r1, r2, r3;
            ldsm_x4(r0, r1, r2, r3, addr);
            bf[h * 2][0] = r0;     bf[h * 2][1] = r1;
            bf[h * 2 + 1][0] = r2; bf[h * 2 + 1][1] = r3;
        }
#pragma unroll
        for (int mt = 0; mt < 4; ++mt)
#pragma unroll
            for (int nt = 0; nt < 4; ++nt)
                mma16816(acc[mt][nt], af[mt], bf[nt]);
    }
}

__global__ void __launch_bounds__(256) k_gemm_mma(float* __restrict__ out) {
    extern __shared__ __align__(128) char smem[];
    const uint32_t sb = smem_u32(smem);
    const int tid = threadIdx.x, lane = tid & 31, wid = tid >> 5;
    const int m0 = blockIdx.x * 128, ct = blockIdx.y;
    const int sel = (ct == 0) ? 0 : 1 + ((ct - 1) >> 1);

    const __nv_bfloat16* Asrc = &g_Abf[sel][m0][0];
    // ---- group 0: A_hi (chunks 0..15 per row) + W_hi ----
#pragma unroll
    for (int it = 0; it < 8; ++it) {
        int idx = it * 256 + tid;
        int row = idx >> 4, q = idx & 15;                      // hi chunks
        cp16(sb + row * 512 + (((q & 24) | ((q ^ row) & 7)) * 16), Asrc + row * 256 + q * 8);
    }
#pragma unroll
    for (int it = 0; it < 8; ++it) {
        int idx = it * 256 + tid;
        int row = idx >> 4, q = idx & 15;
        cp16(sb + 65536 + row * 256 + (((q & 8) | ((q ^ row) & 7)) * 16),
             &g_Wbf[0][ct * 128 + row][q * 8]);
    }
    cp_commit();
    // ---- group 1: A_lo (chunks 16..31) + W_lo ----
#pragma unroll
    for (int it = 0; it < 8; ++it) {
        int idx = it * 256 + tid;
        int row = idx >> 4, q = 16 + (idx & 15);               // lo chunks
        cp16(sb + row * 512 + (((q & 24) | ((q ^ row) & 7)) * 16), Asrc + row * 256 + q * 8);
    }
#pragma unroll
    for (int it = 0; it < 8; ++it) {
        int idx = it * 256 + tid;
        int row = idx >> 4, q = idx & 15;
        cp16(sb + 65536 + 32768 + row * 256 + (((q & 8) | ((q ^ row) & 7)) * 16),
             &g_Wbf[1][ct * 128 + row][q * 8]);
    }
    cp_commit();

    const int wm = wid >> 2, wn = wid & 3;
    float acc[4][4][4];
#pragma unroll
    for (int i = 0; i < 4; ++i)
#pragma unroll
        for (int j = 0; j < 4; ++j)
#pragma unroll
            for (int k = 0; k < 4; ++k) acc[i][j][k] = 0.0f;

    const int a_lrow = wm * 64 + (lane & 15);
    const int a_lsel = lane >> 4;
    const int b_lrow0 = wn * 32 + ((lane >> 4) << 3) + (lane & 7);
    const int b_lsel = (lane >> 3) & 1;

    cp_wait<1>();
    __syncthreads();
    gemm_pass(sb, 0, 0, a_lrow, a_lsel, b_lrow0, b_lsel, acc);      // hi*hi
    cp_wait<0>();
    __syncthreads();
    gemm_pass(sb, 16, 0, a_lrow, a_lsel, b_lrow0, b_lsel, acc);     // lo*hi
    gemm_pass(sb, 0, 32768, a_lrow, a_lsel, b_lrow0, b_lsel, acc);  // hi*lo

    // ---- epilogue ----
    const int er = lane >> 2, ec = (lane & 3) * 2;
    if (ct == 0) {
#pragma unroll
        for (int mt = 0; mt < 4; ++mt)
#pragma unroll
            for (int nt = 0; nt < 4; ++nt) {
                int row = m0 + wm * 64 + mt * 16 + er;
                int col = wn * 32 + nt * 8 + ec;
                *(float2*)&out[row * 128 + col]       = make_float2(acc[mt][nt][0], acc[mt][nt][1]);
                *(float2*)&out[(row + 8) * 128 + col] = make_float2(acc[mt][nt][2], acc[mt][nt][3]);
            }
    } else {
#pragma unroll
        for (int mt = 0; mt < 4; ++mt)
#pragma unroll
            for (int nt = 0; nt < 4; ++nt) {
                int row = m0 + wm * 64 + mt * 16 + er;
                int col = (ct - 1) * 128 + wn * 32 + nt * 8 + ec;
                *(float2*)&g_Cs[row * 1024 + col]       = make_float2(acc[mt][nt][0], acc[mt][nt][1]);
                *(float2*)&g_Cs[(row + 8) * 1024 + col] = make_float2(acc[mt][nt][2], acc[mt][nt][3]);
            }
    }
}

// ---- K3: finalize. out[n,o] += sum_jp Cs[n, jp*256 + q*8 + cfl[n,q,jp] + r2] ----
__global__ void __launch_bounds__(256) k_final(float* __restrict__ out) {
    int idx = blockIdx.x * 256 + threadIdx.x;
    int n = idx >> 7, o = idx & 127;
    int q = o >> 2, r2 = o & 3;
    float acc = out[idx];
    uint32_t cf4 = *(const uint32_t*)&g_cflp[n * 128 + q * 4];
    const float* Cs = g_Cs + n * 1024 + q * 8 + r2;
    float t0 = Cs[(cf4 & 0xFF)];
    float t1 = Cs[256 + ((cf4 >> 8) & 0xFF)];
    float t2 = Cs[512 + ((cf4 >> 16) & 0xFF)];
    float t3 = Cs[768 + (cf4 >> 24)];
    out[idx] = acc + (t0 + t1) + (t2 + t3);
}

extern "C" void kernel_launch(void* const* d_in, const int* in_sizes, int n_in,
                              void* d_out, int out_size) {
    const float* x  = (const float*)d_in[0];
    const float* bw = (const float*)d_in[1];
    const float* sw = (const float*)d_in[2];
    float* out = (float*)d_out;
    int N = in_sizes[0] / FIN;
    if (N > MAXN) N = MAXN;

    const int smem = 65536 + 65536;  // 128 KB
    cudaFuncSetAttribute(k_gemm_mma, cudaFuncAttributeMaxDynamicSharedMemorySize, smem);

    int PA = (N * FIN) / 256;
    k_prep<<<PA + 64 + 128, 256>>>(x, bw, sw, PA);
    dim3 grid(N / 128, 9);
    k_gemm_mma<<<grid, 256, smem>>>(out);
    k_final<<<(N * FIN) / 256, 256>>>(out);
}

// round 5
// speedup vs baseline: 1.9625x; 1.0019x over previous
#include <cuda_runtime.h>
#include <cuda_bf16.h>
#include <cstdint>

#define DINLINE __device__ __forceinline__

static constexpr int MAXN = 2048;
static constexpr int FIN  = 128;

// ---- scratch (device globals; no allocation allowed) ----
__device__ __align__(16) __nv_bfloat16 g_Abf[5][MAXN][256]; // [sel][n][0:128)=hi,[128:256)=lo
__device__ __align__(16) __nv_bfloat16 g_Wbf[2][1152][128]; // [hi/lo][c][k] N-major
__device__ __align__(16) float g_Cs[MAXN * 1024];           // spline GEMM out [n][1024]
__device__ unsigned char g_cflp[MAXN * FIN];                // planar [n][jp][q]

// ---------------- PTX helpers ----------------
DINLINE uint32_t smem_u32(const void* p) {
    uint32_t a;
    asm("{ .reg .u64 t; cvta.to.shared.u64 t, %1; cvt.u32.u64 %0, t; }" : "=r"(a) : "l"(p));
    return a;
}
DINLINE void cp16(uint32_t s, const void* g) {
    asm volatile("cp.async.cg.shared.global [%0], [%1], 16;" :: "r"(s), "l"(g));
}
DINLINE void cp_commit() { asm volatile("cp.async.commit_group;"); }
template <int N_> DINLINE void cp_wait() {
    asm volatile("cp.async.wait_group %0;" :: "n"(N_));
}
DINLINE void ldsm_x4(uint32_t& r0, uint32_t& r1, uint32_t& r2, uint32_t& r3, uint32_t addr) {
    asm volatile("ldmatrix.sync.aligned.m8n8.x4.shared.b16 {%0,%1,%2,%3}, [%4];"
                 : "=r"(r0), "=r"(r1), "=r"(r2), "=r"(r3) : "r"(addr));
}
DINLINE void mma16816(float* d, const uint32_t* a, const uint32_t* b) {
    asm volatile(
        "mma.sync.aligned.m16n8k16.row.col.f32.bf16.bf16.f32 "
        "{%0,%1,%2,%3}, {%4,%5,%6,%7}, {%8,%9}, {%0,%1,%2,%3};"
        : "+f"(d[0]), "+f"(d[1]), "+f"(d[2]), "+f"(d[3])
        : "r"(a[0]), "r"(a[1]), "r"(a[2]), "r"(a[3]), "r"(b[0]), "r"(b[1]));
}
// pack hi/lo bf16 split of (a,b) -> two u32 words (a in low half)
DINLINE void split2(float a, float b, uint32_t& hw, uint32_t& lw) {
    __nv_bfloat16 ah = __float2bfloat16(a), bh = __float2bfloat16(b);
    __nv_bfloat162 h; h.x = ah; h.y = bh;
    hw = *(uint32_t*)&h;
    __nv_bfloat162 l;
    l.x = __float2bfloat16(a - __bfloat162float(ah));
    l.y = __float2bfloat16(b - __bfloat162float(bh));
    lw = *(uint32_t*)&l;
}

// ---- K1: all prep, vectorized. Grid: [0,PA8) act; [PA8,PA8+8) baseW; then 128 splineW ----
__global__ void __launch_bounds__(256) k_prep(const float* __restrict__ x,
                                              const float* __restrict__ bw,
                                              const float* __restrict__ sw,
                                              int PA8) {
    __shared__ float tile[32][33];
    const int b = blockIdx.x, t = threadIdx.x;
    if (b < PA8) {
        int idx8 = b * 256 + t;                 // 16B-chunk id
        int n = idx8 >> 4, c = idx8 & 15;
        const float4* xp = (const float4*)(x + n * 128 + c * 8);
        float4 x0 = xp[0], x1 = xp[1];
        float xv[8] = {x0.x, x0.y, x0.z, x0.w, x1.x, x1.y, x1.z, x1.w};
        float v[5][8];
        uint32_t cfb[8];
        const float s6 = 0.16666666666666666f;
#pragma unroll
        for (int e = 0; e < 8; ++e) {
            float xe = xv[e];
            v[0][e] = xe / (1.0f + __expf(-xe));
            float xn = fminf(fmaxf(xe, -1.0f), 1.0f);
            float tt = (xn + 2.2f) * 2.5f;
            float fl = floorf(tt);
            float u  = tt - fl;
            int ii = (int)fl; ii = ii < 3 ? 3 : (ii > 7 ? 7 : ii);
            float u2 = u * u;
            v[1][e] = s6 * (1.0f + u * (-3.0f + u * (3.0f - u)));
            v[2][e] = s6 * (4.0f + u2 * (3.0f * u - 6.0f));
            v[3][e] = s6 * (1.0f + u * (3.0f + u * (3.0f - 3.0f * u)));
            v[4][e] = s6 * (u2 * u);
            cfb[e] = (uint32_t)(ii - 3);
        }
#pragma unroll
        for (int s = 0; s < 5; ++s) {
            uint4 hv, lv;
            split2(v[s][0], v[s][1], hv.x, lv.x);
            split2(v[s][2], v[s][3], hv.y, lv.y);
            split2(v[s][4], v[s][5], hv.z, lv.z);
            split2(v[s][6], v[s][7], hv.w, lv.w);
            *(uint4*)&g_Abf[s][n][c * 8]       = hv;
            *(uint4*)&g_Abf[s][n][128 + c * 8] = lv;
        }
        uint2 cw;
        cw.x = cfb[0] | (cfb[1] << 8) | (cfb[2] << 16) | (cfb[3] << 24);
        cw.y = cfb[4] | (cfb[5] << 8) | (cfb[6] << 16) | (cfb[7] << 24);
        // planar: [n][jp][q], jp = c>>2, q = (c&3)*8 + e
        *(uint2*)(g_cflp + n * 128 + (c >> 2) * 32 + (c & 3) * 8) = cw;
    } else if (b < PA8 + 8) {
        int f8 = (b - PA8) * 256 + t;          // chunk: c = f8>>4, ch = f8&15
        int c = f8 >> 4, ch = f8 & 15;
        const float4* wp = (const float4*)(bw + c * 128 + ch * 8);
        float4 w0 = wp[0], w1 = wp[1];
        float wv[8] = {w0.x, w0.y, w0.z, w0.w, w1.x, w1.y, w1.z, w1.w};
        uint4 hv, lv;
        split2(wv[0], wv[1], hv.x, lv.x);
        split2(wv[2], wv[3], hv.y, lv.y);
        split2(wv[4], wv[5], hv.z, lv.z);
        split2(wv[6], wv[7], hv.w, lv.w);
        *(uint4*)&g_Wbf[0][c][ch * 8] = hv;
        *(uint4*)&g_Wbf[1][c][ch * 8] = lv;
    } else {
        int bb = b - PA8 - 8;                  // 0..127
        int bc = bb >> 2, bi = bb & 3;         // c-tile, i-tile (32 each)
        int tx = t & 31, ty = t >> 5;
#pragma unroll
        for (int iy = 0; iy < 4; ++iy) {
            int il = ty + 8 * iy;
            tile[il][tx] = sw[(bi * 32 + il) * 1024 + bc * 32 + tx];  // coalesced in c
        }
        __syncthreads();
        if (t < 128) {
            int cl = t >> 2, ch = t & 3;
            float wv[8];
#pragma unroll
            for (int e = 0; e < 8; ++e) wv[e] = tile[ch * 8 + e][cl];
            uint4 hv, lv;
            split2(wv[0], wv[1], hv.x, lv.x);
            split2(wv[2], wv[3], hv.y, lv.y);
            split2(wv[4], wv[5], hv.z, lv.z);
            split2(wv[6], wv[7], hv.w, lv.w);
            int c = 128 + bc * 32 + cl, i = bi * 32 + ch * 8;
            *(uint4*)&g_Wbf[0][c][i] = hv;
            *(uint4*)&g_Wbf[1][c][i] = lv;
        }
    }
}

// ---- K2: HMMA GEMM, pipelined hi/lo staging. grid (M/128, 9), 256 thr ----
DINLINE void gemm_pass(uint32_t sb, int a_chunk, uint32_t w_off,
                       int a_lrow, int a_lsel, int b_lrow0, int b_lsel,
                       float (&acc)[4][4][4]) {
#pragma unroll
    for (int ks = 0; ks < 8; ++ks) {
        uint32_t af[4][4];
#pragma unroll
        for (int mt = 0; mt < 4; ++mt) {
            int row = a_lrow + mt * 16;
            int q = a_chunk + ks * 2 + a_lsel;
            uint32_t addr = sb + row * 512 + (((q & 24) | ((q ^ row) & 7)) * 16);
            ldsm_x4(af[mt][0], af[mt][1], af[mt][2], af[mt][3], addr);
        }
        uint32_t bf[4][2];
#pragma unroll
        for (int h = 0; h < 2; ++h) {
            int row = b_lrow0 + h * 16;
            int q = ks * 2 + b_lsel;
            uint32_t addr = sb + 65536 + w_off + row * 256 + (((q & 8) | ((q ^ row) & 7)) * 16);
            uint32_t r0, r1, r2, r3;
            ldsm_x4(r0, r1, r2, r3, addr);
            bf[h * 2][0] = r0;     bf[h * 2][1] = r1;
            bf[h * 2 + 1][0] = r2; bf[h * 2 + 1][1] = r3;
        }
#pragma unroll
        for (int mt = 0; mt < 4; ++mt)
#pragma unroll
            for (int nt = 0; nt < 4; ++nt)
                mma16816(acc[mt][nt], af[mt], bf[nt]);
    }
}

__global__ void __launch_bounds__(256) k_gemm_mma(float* __restrict__ out) {
    extern __shared__ __align__(128) char smem[];
    const uint32_t sb = smem_u32(smem);
    const int tid = threadIdx.x, lane = tid & 31, wid = tid >> 5;
    const int m0 = blockIdx.x * 128, ct = blockIdx.y;
    const int sel = (ct == 0) ? 0 : 1 + ((ct - 1) >> 1);

    const __nv_bfloat16* Asrc = &g_Abf[sel][m0][0];
#pragma unroll
    for (int it = 0; it < 8; ++it) {
        int idx = it * 256 + tid;
        int row = idx >> 4, q = idx & 15;
        cp16(sb + row * 512 + (((q & 24) | ((q ^ row) & 7)) * 16), Asrc + row * 256 + q * 8);
    }
#pragma unroll
    for (int it = 0; it < 8; ++it) {
        int idx = it * 256 + tid;
        int row = idx >> 4, q = idx & 15;
        cp16(sb + 65536 + row * 256 + (((q & 8) | ((q ^ row) & 7)) * 16),
             &g_Wbf[0][ct * 128 + row][q * 8]);
    }
    cp_commit();
#pragma unroll
    for (int it = 0; it < 8; ++it) {
        int idx = it * 256 + tid;
        int row = idx >> 4, q = 16 + (idx & 15);
        cp16(sb + row * 512 + (((q & 24) | ((q ^ row) & 7)) * 16), Asrc + row * 256 + q * 8);
    }
#pragma unroll
    for (int it = 0; it < 8; ++it) {
        int idx = it * 256 + tid;
        int row = idx >> 4, q = idx & 15;
        cp16(sb + 65536 + 32768 + row * 256 + (((q & 8) | ((q ^ row) & 7)) * 16),
             &g_Wbf[1][ct * 128 + row][q * 8]);
    }
    cp_commit();

    const int wm = wid >> 2, wn = wid & 3;
    float acc[4][4][4];
#pragma unroll
    for (int i = 0; i < 4; ++i)
#pragma unroll
        for (int j = 0; j < 4; ++j)
#pragma unroll
            for (int k = 0; k < 4; ++k) acc[i][j][k] = 0.0f;

    const int a_lrow = wm * 64 + (lane & 15);
    const int a_lsel = lane >> 4;
    const int b_lrow0 = wn * 32 + ((lane >> 4) << 3) + (lane & 7);
    const int b_lsel = (lane >> 3) & 1;

    cp_wait<1>();
    __syncthreads();
    gemm_pass(sb, 0, 0, a_lrow, a_lsel, b_lrow0, b_lsel, acc);      // hi*hi
    cp_wait<0>();
    __syncthreads();
    gemm_pass(sb, 16, 0, a_lrow, a_lsel, b_lrow0, b_lsel, acc);     // lo*hi
    gemm_pass(sb, 0, 32768, a_lrow, a_lsel, b_lrow0, b_lsel, acc);  // hi*lo

    const int er = lane >> 2, ec = (lane & 3) * 2;
    if (ct == 0) {
#pragma unroll
        for (int mt = 0; mt < 4; ++mt)
#pragma unroll
            for (int nt = 0; nt < 4; ++nt) {
                int row = m0 + wm * 64 + mt * 16 + er;
                int col = wn * 32 + nt * 8 + ec;
                *(float2*)&out[row * 128 + col]       = make_float2(acc[mt][nt][0], acc[mt][nt][1]);
                *(float2*)&out[(row + 8) * 128 + col] = make_float2(acc[mt][nt][2], acc[mt][nt][3]);
            }
    } else {
#pragma unroll
        for (int mt = 0; mt < 4; ++mt)
#pragma unroll
            for (int nt = 0; nt < 4; ++nt) {
                int row = m0 + wm * 64 + mt * 16 + er;
                int col = (ct - 1) * 128 + wn * 32 + nt * 8 + ec;
                *(float2*)&g_Cs[row * 1024 + col]       = make_float2(acc[mt][nt][0], acc[mt][nt][1]);
                *(float2*)&g_Cs[(row + 8) * 1024 + col] = make_float2(acc[mt][nt][2], acc[mt][nt][3]);
            }
    }
}

// ---- K3: finalize. out[n,o] += sum_jp Cs[n, jp*256 + q*8 + cfl[n,jp,q] + r2] ----
__global__ void __launch_bounds__(256) k_final(float* __restrict__ out) {
    int idx = blockIdx.x * 256 + threadIdx.x;
    int n = idx >> 7, o = idx & 127;
    int q = o >> 2, r2 = o & 3;
    float acc = out[idx];
    const unsigned char* cf = g_cflp + n * 128 + q;
    const float* Cs = g_Cs + n * 1024 + q * 8 + r2;
    float t0 = Cs[cf[0]];
    float t1 = Cs[256 + cf[32]];
    float t2 = Cs[512 + cf[64]];
    float t3 = Cs[768 + cf[96]];
    out[idx] = acc + (t0 + t1) + (t2 + t3);
}

extern "C" void kernel_launch(void* const* d_in, const int* in_sizes, int n_in,
                              void* d_out, int out_size) {
    const float* x  = (const float*)d_in[0];
    const float* bw = (const float*)d_in[1];
    const float* sw = (const float*)d_in[2];
    float* out = (float*)d_out;
    int N = in_sizes[0] / FIN;
    if (N > MAXN) N = MAXN;

    const int smem = 65536 + 65536;  // 128 KB
    cudaFuncSetAttribute(k_gemm_mma, cudaFuncAttributeMaxDynamicSharedMemorySize, smem);

    int PA8 = (N * FIN) / 2048;      // activation blocks (8 elems/thread)
    k_prep<<<PA8 + 8 + 128, 256>>>(x, bw, sw, PA8);
    dim3 grid(N / 128, 9);
    k_gemm_mma<<<grid, 256, smem>>>(out);
    k_final<<<(N * FIN) / 256, 256>>>(out);
}

// round 6
// speedup vs baseline: 2.0671x; 1.0533x over previous
#include <cuda_runtime.h>
#include <cuda_bf16.h>
#include <cstdint>

#define DINLINE __device__ __forceinline__

static constexpr int MAXN = 2048;
static constexpr int FIN  = 128;

// ---- scratch (device globals; no allocation allowed) ----
__device__ __align__(16) __nv_bfloat16 g_Abf[5][MAXN][256]; // [sel][n][0:128)=hi,[128:256)=lo
__device__ __align__(16) __nv_bfloat16 g_Wbf[2][1152][128]; // [hi/lo][c][k] N-major
__device__ __align__(16) float g_Cs[MAXN * 1024];           // spline GEMM out [n][1024]
__device__ unsigned char g_cflp[MAXN * FIN];                // planar [n][jp][q]

// ---------------- PTX helpers ----------------
DINLINE uint32_t smem_u32(const void* p) {
    uint32_t a;
    asm("{ .reg .u64 t; cvta.to.shared.u64 t, %1; cvt.u32.u64 %0, t; }" : "=r"(a) : "l"(p));
    return a;
}
DINLINE void cp16(uint32_t s, const void* g) {
    asm volatile("cp.async.cg.shared.global [%0], [%1], 16;" :: "r"(s), "l"(g));
}
DINLINE void cp_commit() { asm volatile("cp.async.commit_group;"); }
template <int N_> DINLINE void cp_wait() {
    asm volatile("cp.async.wait_group %0;" :: "n"(N_));
}
DINLINE void ldsm_x4(uint32_t& r0, uint32_t& r1, uint32_t& r2, uint32_t& r3, uint32_t addr) {
    asm volatile("ldmatrix.sync.aligned.m8n8.x4.shared.b16 {%0,%1,%2,%3}, [%4];"
                 : "=r"(r0), "=r"(r1), "=r"(r2), "=r"(r3) : "r"(addr));
}
DINLINE void mma16816(float* d, const uint32_t* a, const uint32_t* b) {
    asm volatile(
        "mma.sync.aligned.m16n8k16.row.col.f32.bf16.bf16.f32 "
        "{%0,%1,%2,%3}, {%4,%5,%6,%7}, {%8,%9}, {%0,%1,%2,%3};"
        : "+f"(d[0]), "+f"(d[1]), "+f"(d[2]), "+f"(d[3])
        : "r"(a[0]), "r"(a[1]), "r"(a[2]), "r"(a[3]), "r"(b[0]), "r"(b[1]));
}
// pack hi/lo bf16 split of (a,b) -> two u32 words (a in low half)
DINLINE void split2(float a, float b, uint32_t& hw, uint32_t& lw) {
    __nv_bfloat16 ah = __float2bfloat16(a), bh = __float2bfloat16(b);
    __nv_bfloat162 h; h.x = ah; h.y = bh;
    hw = *(uint32_t*)&h;
    __nv_bfloat162 l;
    l.x = __float2bfloat16(a - __bfloat162float(ah));
    l.y = __float2bfloat16(b - __bfloat162float(bh));
    lw = *(uint32_t*)&l;
}

// ---- K1: all prep. Grid: [0,PA4) act (4 elems/thr); [PA4,PA4+8) baseW; then 128 splineW ----
__global__ void __launch_bounds__(256) k_prep(const float* __restrict__ x,
                                              const float* __restrict__ bw,
                                              const float* __restrict__ sw,
                                              int PA4) {
    __shared__ float tile[32][33];
    const int b = blockIdx.x, t = threadIdx.x;
    if (b < PA4) {
        int idx4 = b * 256 + t;                 // 4-element chunk id
        int n = idx4 >> 5, c4 = idx4 & 31;
        float4 x0 = *(const float4*)(x + n * 128 + c4 * 4);
        float xv[4] = {x0.x, x0.y, x0.z, x0.w};
        float v[5][4];
        uint32_t cfb[4];
        const float s6 = 0.16666666666666666f;
#pragma unroll
        for (int e = 0; e < 4; ++e) {
            float xe = xv[e];
            v[0][e] = xe / (1.0f + __expf(-xe));
            float xn = fminf(fmaxf(xe, -1.0f), 1.0f);
            float tt = (xn + 2.2f) * 2.5f;
            float fl = floorf(tt);
            float u  = tt - fl;
            int ii = (int)fl; ii = ii < 3 ? 3 : (ii > 7 ? 7 : ii);
            float u2 = u * u;
            v[1][e] = s6 * (1.0f + u * (-3.0f + u * (3.0f - u)));
            v[2][e] = s6 * (4.0f + u2 * (3.0f * u - 6.0f));
            v[3][e] = s6 * (1.0f + u * (3.0f + u * (3.0f - 3.0f * u)));
            v[4][e] = s6 * (u2 * u);
            cfb[e] = (uint32_t)(ii - 3);
        }
#pragma unroll
        for (int s = 0; s < 5; ++s) {
            uint2 hv, lv;
            split2(v[s][0], v[s][1], hv.x, lv.x);
            split2(v[s][2], v[s][3], hv.y, lv.y);
            *(uint2*)&g_Abf[s][n][c4 * 4]       = hv;
            *(uint2*)&g_Abf[s][n][128 + c4 * 4] = lv;
        }
        uint32_t cw = cfb[0] | (cfb[1] << 8) | (cfb[2] << 16) | (cfb[3] << 24);
        // planar [n][jp][q]: jp = c4>>3 (const per thread), q = (c4&7)*4 + e
        *(uint32_t*)(g_cflp + n * 128 + (c4 >> 3) * 32 + (c4 & 7) * 4) = cw;
    } else if (b < PA4 + 8) {
        int f8 = (b - PA4) * 256 + t;          // 8-elem chunk: c = f8>>4, ch = f8&15
        int c = f8 >> 4, ch = f8 & 15;
        const float4* wp = (const float4*)(bw + c * 128 + ch * 8);
        float4 w0 = wp[0], w1 = wp[1];
        float wv[8] = {w0.x, w0.y, w0.z, w0.w, w1.x, w1.y, w1.z, w1.w};
        uint4 hv, lv;
        split2(wv[0], wv[1], hv.x, lv.x);
        split2(wv[2], wv[3], hv.y, lv.y);
        split2(wv[4], wv[5], hv.z, lv.z);
        split2(wv[6], wv[7], hv.w, lv.w);
        *(uint4*)&g_Wbf[0][c][ch * 8] = hv;
        *(uint4*)&g_Wbf[1][c][ch * 8] = lv;
    } else {
        int bb = b - PA4 - 8;                  // 0..127
        int bc = bb >> 2, bi = bb & 3;         // c-tile, i-tile (32 each)
        int tx = t & 31, ty = t >> 5;
#pragma unroll
        for (int iy = 0; iy < 4; ++iy) {
            int il = ty + 8 * iy;
            tile[il][tx] = sw[(bi * 32 + il) * 1024 + bc * 32 + tx];  // coalesced in c
        }
        __syncthreads();
        {
            int cl = t >> 3, ch = t & 7;       // all 256 threads: 4 elems each
            float wv[4];
#pragma unroll
            for (int e = 0; e < 4; ++e) wv[e] = tile[ch * 4 + e][cl];
            uint2 hv, lv;
            split2(wv[0], wv[1], hv.x, lv.x);
            split2(wv[2], wv[3], hv.y, lv.y);
            int c = 128 + bc * 32 + cl, i = bi * 32 + ch * 4;
            *(uint2*)&g_Wbf[0][c][i] = hv;
            *(uint2*)&g_Wbf[1][c][i] = lv;
        }
    }
}

// ---- K2: HMMA GEMM, pipelined hi/lo staging. grid (M/128, 9), 256 thr ----
DINLINE void gemm_pass(uint32_t sb, int a_chunk, uint32_t w_off,
                       int a_lrow, int a_lsel, int b_lrow0, int b_lsel,
                       float (&acc)[4][4][4]) {
#pragma unroll
    for (int ks = 0; ks < 8; ++ks) {
        uint32_t af[4][4];
#pragma unroll
        for (int mt = 0; mt < 4; ++mt) {
            int row = a_lrow + mt * 16;
            int q = a_chunk + ks * 2 + a_lsel;
            uint32_t addr = sb + row * 512 + (((q & 24) | ((q ^ row) & 7)) * 16);
            ldsm_x4(af[mt][0], af[mt][1], af[mt][2], af[mt][3], addr);
        }
        uint32_t bf[4][2];
#pragma unroll
        for (int h = 0; h < 2; ++h) {
            int row = b_lrow0 + h * 16;
            int q = ks * 2 + b_lsel;
            uint32_t addr = sb + 65536 + w_off + row * 256 + (((q & 8) | ((q ^ row) & 7)) * 16);
            uint32_t r0, r1, r2, r3;
            ldsm_x4(r0, r1, r2, r3, addr);
            bf[h * 2][0] = r0;     bf[h * 2][1] = r1;
            bf[h * 2 + 1][0] = r2; bf[h * 2 + 1][1] = r3;
        }
#pragma unroll
        for (int mt = 0; mt < 4; ++mt)
#pragma unroll
            for (int nt = 0; nt < 4; ++nt)
                mma16816(acc[mt][nt], af[mt], bf[nt]);
    }
}

__global__ void __launch_bounds__(256) k_gemm_mma(float* __restrict__ out) {
    extern __shared__ __align__(128) char smem[];
    const uint32_t sb = smem_u32(smem);
    const int tid = threadIdx.x, lane = tid & 31, wid = tid >> 5;
    const int m0 = blockIdx.x * 128, ct = blockIdx.y;
    const int sel = (ct == 0) ? 0 : 1 + ((ct - 1) >> 1);

    const __nv_bfloat16* Asrc = &g_Abf[sel][m0][0];
#pragma unroll
    for (int it = 0; it < 8; ++it) {
        int idx = it * 256 + tid;
        int row = idx >> 4, q = idx & 15;
        cp16(sb + row * 512 + (((q & 24) | ((q ^ row) & 7)) * 16), Asrc + row * 256 + q * 8);
    }
#pragma unroll
    for (int it = 0; it < 8; ++it) {
        int idx = it * 256 + tid;
        int row = idx >> 4, q = idx & 15;
        cp16(sb + 65536 + row * 256 + (((q & 8) | ((q ^ row) & 7)) * 16),
             &g_Wbf[0][ct * 128 + row][q * 8]);
    }
    cp_commit();
#pragma unroll
    for (int it = 0; it < 8; ++it) {
        int idx = it * 256 + tid;
        int row = idx >> 4, q = 16 + (idx & 15);
        cp16(sb + row * 512 + (((q & 24) | ((q ^ row) & 7)) * 16), Asrc + row * 256 + q * 8);
    }
#pragma unroll
    for (int it = 0; it < 8; ++it) {
        int idx = it * 256 + tid;
        int row = idx >> 4, q = idx & 15;
        cp16(sb + 65536 + 32768 + row * 256 + (((q & 8) | ((q ^ row) & 7)) * 16),
             &g_Wbf[1][ct * 128 + row][q * 8]);
    }
    cp_commit();

    const int wm = wid >> 2, wn = wid & 3;
    float acc[4][4][4];
#pragma unroll
    for (int i = 0; i < 4; ++i)
#pragma unroll
        for (int j = 0; j < 4; ++j)
#pragma unroll
            for (int k = 0; k < 4; ++k) acc[i][j][k] = 0.0f;

    const int a_lrow = wm * 64 + (lane & 15);
    const int a_lsel = lane >> 4;
    const int b_lrow0 = wn * 32 + ((lane >> 4) << 3) + (lane & 7);
    const int b_lsel = (lane >> 3) & 1;

    cp_wait<1>();
    __syncthreads();
    gemm_pass(sb, 0, 0, a_lrow, a_lsel, b_lrow0, b_lsel, acc);      // hi*hi
    cp_wait<0>();
    __syncthreads();
    gemm_pass(sb, 16, 0, a_lrow, a_lsel, b_lrow0, b_lsel, acc);     // lo*hi
    gemm_pass(sb, 0, 32768, a_lrow, a_lsel, b_lrow0, b_lsel, acc);  // hi*lo

    const int er = lane >> 2, ec = (lane & 3) * 2;
    if (ct == 0) {
#pragma unroll
        for (int mt = 0; mt < 4; ++mt)
#pragma unroll
            for (int nt = 0; nt < 4; ++nt) {
                int row = m0 + wm * 64 + mt * 16 + er;
                int col = wn * 32 + nt * 8 + ec;
                *(float2*)&out[row * 128 + col]       = make_float2(acc[mt][nt][0], acc[mt][nt][1]);
                *(float2*)&out[(row + 8) * 128 + col] = make_float2(acc[mt][nt][2], acc[mt][nt][3]);
            }
    } else {
#pragma unroll
        for (int mt = 0; mt < 4; ++mt)
#pragma unroll
            for (int nt = 0; nt < 4; ++nt) {
                int row = m0 + wm * 64 + mt * 16 + er;
                int col = (ct - 1) * 128 + wn * 32 + nt * 8 + ec;
                *(float2*)&g_Cs[row * 1024 + col]       = make_float2(acc[mt][nt][0], acc[mt][nt][1]);
                *(float2*)&g_Cs[(row + 8) * 1024 + col] = make_float2(acc[mt][nt][2], acc[mt][nt][3]);
            }
    }
}

// ---- K3: finalize. out[n,o] += sum_jp Cs[n, jp*256 + q*8 + cfl[n,jp,q] + r2] ----
__global__ void __launch_bounds__(256) k_final(float* __restrict__ out) {
    int idx = blockIdx.x * 256 + threadIdx.x;
    int n = idx >> 7, o = idx & 127;
    int q = o >> 2, r2 = o & 3;
    float acc = out[idx];
    const unsigned char* cf = g_cflp + n * 128 + q;
    const float* Cs = g_Cs + n * 1024 + q * 8 + r2;
    float t0 = Cs[cf[0]];
    float t1 = Cs[256 + cf[32]];
    float t2 = Cs[512 + cf[64]];
    float t3 = Cs[768 + cf[96]];
    out[idx] = acc + (t0 + t1) + (t2 + t3);
}

extern "C" void kernel_launch(void* const* d_in, const int* in_sizes, int n_in,
                              void* d_out, int out_size) {
    const float* x  = (const float*)d_in[0];
    const float* bw = (const float*)d_in[1];
    const float* sw = (const float*)d_in[2];
    float* out = (float*)d_out;
    int N = in_sizes[0] / FIN;
    if (N > MAXN) N = MAXN;

    const int smem = 65536 + 65536;  // 128 KB
    cudaFuncSetAttribute(k_gemm_mma, cudaFuncAttributeMaxDynamicSharedMemorySize, smem);

    int PA4 = (N * FIN) / 1024;      // activation blocks (4 elems/thread)
    k_prep<<<PA4 + 8 + 128, 256>>>(x, bw, sw, PA4);
    dim3 grid(N / 128, 9);
    k_gemm_mma<<<grid, 256, smem>>>(out);
    k_final<<<(N * FIN) / 256, 256>>>(out);
}